// round 2
// baseline (speedup 1.0000x reference)
#include <cuda_runtime.h>
#include <cstdint>

#define BNUM 4
#define HS 64
#define WS 64
#define HU 512
#define WU 512
#define CORI 90
#define CMNT 180
#define COFF 8
#define KCAND 1024
#define NCELL (HS*WS)       // 4096
#define NPIX (HU*WU)        // 262144

// output layout: minut [4,1024,4] | keep [4,1024] | enh_vis | mask_up*255 | ori_field
#define MINUT_OFF 0
#define KEEP_OFF  16384
#define ENH_OFF   20480
#define MASK_OFF  1069056
#define ORI_OFF   2117632

__device__ float g_tA[BNUM*NPIX];
__device__ float g_tB[BNUM*NPIX];
__device__ float g_maskup[BNUM*NPIX];
__device__ unsigned g_emin[BNUM];
__device__ unsigned g_emax[BNUM];

__device__ __forceinline__ unsigned f2ord(float f){
    unsigned u=__float_as_uint(f);
    return (u & 0x80000000u) ? ~u : (u | 0x80000000u);
}
__device__ __forceinline__ float ord2f(unsigned u){
    u = (u & 0x80000000u) ? (u & 0x7fffffffu) : ~u;
    return __uint_as_float(u);
}

// ---------------- vertical pool: van Herk, window [y-19, y+20] ----------------
// grid: (WU/128, 13 segments, BNUM), block 128. Each thread: one column x,
// 40 outputs. suf[] fully unrolled -> registers.
template<bool MN, bool RND, bool INIT>
__global__ void vpool(const float* __restrict__ in, float* __restrict__ outb){
    if(INIT && blockIdx.x==0 && blockIdx.y==0 && blockIdx.z==0 && threadIdx.x<BNUM){
        g_emin[threadIdx.x]=0xFFFFFFFFu; g_emax[threadIdx.x]=0u;
    }
    int x = blockIdx.x*128 + threadIdx.x;
    int y0 = blockIdx.y*40;
    int b = blockIdx.z;
    const float* s = in  + (size_t)b*NPIX;
    float*       o = outb+ (size_t)b*NPIX;
    const float NEU = MN?1e30f:-1e30f;
    float suf[40];
    float run = NEU;
    #pragma unroll
    for(int d=39; d>=0; --d){
        int yy=y0-19+d;
        float v = (yy>=0 && yy<HU) ? s[yy*WU+x] : NEU;
        if(RND) v=rintf(v);
        run = MN?fminf(run,v):fmaxf(run,v);
        suf[d]=run;
    }
    float pre = NEU;
    #pragma unroll
    for(int j=0;j<40;j++){
        if(j>0){
            int yy=y0+20+j;
            float v = (yy<HU) ? s[yy*WU+x] : NEU;
            if(RND) v=rintf(v);
            pre = MN?fminf(pre,v):fmaxf(pre,v);
        }
        int y=y0+j;
        if(y<HU) o[y*WU+x] = MN?fminf(suf[j],pre):fmaxf(suf[j],pre);
    }
}

// ---------------- horizontal pool: log-doubling tree in shared ----------------
// one block per row. padded row 551 (19 left, 20 right neutral).
// win40[x] = op(run32[x], run8[x+32])
template<bool MN, bool FUSED>
__global__ void hpool(const float* __restrict__ in, float* __restrict__ outb,
                      const float* __restrict__ enh, float* __restrict__ outg){
    __shared__ float sA[552], sB[552], s8[552];
    __shared__ float rmn[8], rmx[8];
    int row = blockIdx.x, b = blockIdx.y, tid = threadIdx.x;
    const float* src = in + ((size_t)b*HU + row)*WU;
    const float NEU = MN?1e30f:-1e30f;
    #define OPX(a,c) (MN?fminf(a,c):fmaxf(a,c))
    for(int i=tid;i<551;i+=256) sA[i] = (i>=19 && i<19+WU) ? src[i-19] : NEU;
    __syncthreads();
    for(int i=tid;i<550;i+=256) sB[i]=OPX(sA[i],sA[i+1]);
    __syncthreads();
    for(int i=tid;i<548;i+=256) sA[i]=OPX(sB[i],sB[i+2]);
    __syncthreads();
    for(int i=tid;i<544;i+=256) s8[i]=OPX(sA[i],sA[i+4]);
    __syncthreads();
    for(int i=tid;i<536;i+=256) sB[i]=OPX(s8[i],s8[i+8]);
    __syncthreads();
    for(int i=tid;i<520;i+=256) sA[i]=OPX(sB[i],sB[i+16]);
    __syncthreads();
    float* dst = outb + ((size_t)b*HU+row)*WU;
    if(!FUSED){
        for(int x=tid;x<WU;x+=256) dst[x]=OPX(sA[x], s8[x+32]);
    } else {
        const float* erow = enh + ((size_t)b*HU+row)*WU;
        float mn=1e30f, mx=-1e30f;
        for(int x=tid;x<WU;x+=256){
            float m=OPX(sA[x], s8[x+32]);
            dst[x]=m;
            outg[MASK_OFF + ((size_t)b*HU+row)*WU + x] = m*255.0f;
            float ev = erow[x]*m;
            mn=fminf(mn,ev); mx=fmaxf(mx,ev);
        }
        #pragma unroll
        for(int o=16;o;o>>=1){
            mn=fminf(mn,__shfl_xor_sync(0xFFFFFFFFu,mn,o));
            mx=fmaxf(mx,__shfl_xor_sync(0xFFFFFFFFu,mx,o));
        }
        int lane=tid&31, w=tid>>5;
        if(lane==0){ rmn[w]=mn; rmx[w]=mx; }
        __syncthreads();
        if(tid==0){
            for(int i=1;i<8;i++){ mn=fminf(mn,rmn[i]); mx=fmaxf(mx,rmx[i]); }
            atomicMin(&g_emin[b], f2ord(mn));
            atomicMax(&g_emax[b], f2ord(mx));
        }
    }
    #undef OPX
}

// ---------------- detect: fused 5x5 opening + top-k + NMS, one block/batch ----
__global__ void __launch_bounds__(1024) detect_nms(
    const float* __restrict__ seg,    const float* __restrict__ mscore,
    const float* __restrict__ mori,   const float* __restrict__ mxo,
    const float* __restrict__ myo,    float* __restrict__ out)
{
    int b=blockIdx.x, tid=threadIdx.x;
    __shared__ unsigned long long keys[4096];   // 32KB, aliased heavily
    __shared__ int s_nv;
    float* f0=(float*)keys;       // 4096 floats
    float* f1=f0+4096;            // 4096 floats

    const float* sg = seg    + (size_t)b*NCELL;
    const float* sc = mscore + (size_t)b*NCELL;

    // 1) rounded segmentation into shared
    for(int t=tid;t<NCELL;t+=1024) f0[t]=rintf(sg[t]);
    __syncthreads();
    // 2) erosion 5x5 (clamped) f0 -> f1
    for(int t=tid;t<NCELL;t+=1024){
        int r=t>>6, c=t&63;
        int y0=max(r-2,0), y1=min(r+2,HS-1), x0=max(c-2,0), x1=min(c+2,WS-1);
        float m=1e30f;
        for(int y=y0;y<=y1;y++)
            for(int x=x0;x<=x1;x++)
                m=fminf(m,f0[(y<<6)+x]);
        f1[t]=m;
    }
    __syncthreads();
    // 3) dilation 5x5 into registers; build masked scores
    float mvreg[4]; bool anyv=false;
    #pragma unroll
    for(int k=0;k<4;k++){
        int t=tid+k*1024;
        int r=t>>6, c=t&63;
        int y0=max(r-2,0), y1=min(r+2,HS-1), x0=max(c-2,0), x1=min(c+2,WS-1);
        float mk=-1e30f;
        for(int y=y0;y<=y1;y++)
            for(int x=x0;x<=x1;x++)
                mk=fmaxf(mk,f1[(y<<6)+x]);
        float v=sc[t]*mk;
        bool val = v>0.5f;
        anyv |= val;
        mvreg[k] = val ? v : -1.0f;
    }
    __syncthreads();   // all f1 reads done before keys overwrite
    #pragma unroll
    for(int k=0;k<4;k++){
        int t=tid+k*1024;
        keys[t] = ((unsigned long long)(~f2ord(mvreg[k]))<<32) | (unsigned)t;
    }
    if(__syncthreads_count(anyv)==0){
        float* om=out + MINUT_OFF + (size_t)b*KCAND*4 + (size_t)tid*4;
        om[0]=0.0f; om[1]=0.0f; om[2]=0.0f; om[3]=0.0f;
        out[KEEP_OFF + (size_t)b*KCAND + tid]=0.0f;
        return;
    }
    // bitonic sort 4096 ascending (== descending masked score, ties: smaller idx)
    for(int k=2;k<=4096;k<<=1){
        for(int j=k>>1;j>0;j>>=1){
            for(int i=tid;i<4096;i+=1024){
                int ixj=i^j;
                if(ixj>i){
                    unsigned long long a=keys[i], c=keys[ixj];
                    bool up=((i&k)==0);
                    if((a>c)==up){ keys[i]=c; keys[ixj]=a; }
                }
            }
            __syncthreads();
        }
    }
    unsigned long long key=keys[tid];
    int idx=(int)(key & 0xFFFFFFFFull);
    float mv = ord2f(~(unsigned)(key>>32));
    bool valid = mv>0.5f;
    float score = valid ? mv : 0.0f;
    float xc=0.0f, yc=0.0f, ang=0.0f;
    if(valid){
        int r=idx>>6, c=idx&63;
        const float* o=mori+(size_t)b*CMNT*NCELL+idx;
        int ai=0; float bv=o[0];
        for(int ch=1;ch<CMNT;ch++){ float v=o[(size_t)ch*NCELL]; if(v>bv){bv=v;ai=ch;} }
        const float* xo=mxo+(size_t)b*COFF*NCELL+idx;
        int xi=0; float bx=xo[0];
        for(int ch=1;ch<COFF;ch++){ float v=xo[(size_t)ch*NCELL]; if(v>bx){bx=v;xi=ch;} }
        const float* yo=myo+(size_t)b*COFF*NCELL+idx;
        int yi=0; float by=yo[0];
        for(int ch=1;ch<COFF;ch++){ float v=yo[(size_t)ch*NCELL]; if(v>by){by=v;yi=ch;} }
        ang=((float)ai*2.0f-89.0f)*0.017453292519943295f;
        xc=(float)c*8.0f+(float)xi;
        yc=(float)r*8.0f+(float)yi;
    }
    if(tid==0) s_nv=0;
    __syncthreads();                 // keys reads done before aliased writes
    float* sx=(float*)(keys+1024);
    float* sy=(float*)(keys+1536);
    float* sa=(float*)(keys+2048);
    unsigned char* skeep=(unsigned char*)(keys+2560);
    sx[tid]=xc; sy[tid]=yc; sa[tid]=ang; skeep[tid]=valid?1:0;
    atomicMax(&s_nv, valid?(tid+1):0);
    __syncthreads();
    int nv=s_nv;
    for(int i=0;i<nv;i++){
        if(skeep[i] && tid>i && skeep[tid]){
            float dx=sx[tid]-sx[i], dy=sy[tid]-sy[i];
            float d=sqrtf(dx*dx+dy*dy);
            float da=fabsf(sa[tid]-sa[i]);
            da=fminf(da, 6.2831853071795864f-da);
            if(d<16.0f && da<0.52359877559829887f) skeep[tid]=0;
        }
        __syncthreads();
    }
    float kf = skeep[tid]?1.0f:0.0f;
    float* om=out + MINUT_OFF + (size_t)b*KCAND*4 + (size_t)tid*4;
    om[0]=kf*xc; om[1]=kf*yc; om[2]=kf*ang; om[3]=kf*score;
    out[KEEP_OFF + (size_t)b*KCAND + tid]=kf;
}

// ---------------- finalize: enh_vis + ori_field (mask-predicated) -------------
__global__ void finalize(const float* __restrict__ enh, const float* __restrict__ oriup,
                         float* __restrict__ out){
    int i=blockIdx.x*blockDim.x+threadIdx.x;
    if(i>=BNUM*NPIX) return;
    int b=i/NPIX, p=i%NPIX;
    float m=g_maskup[i];
    float emin=ord2f(g_emin[b]);
    float emax=ord2f(g_emax[b]);
    float e=enh[i]*m;
    out[ENH_OFF+i]=(e-emin)/(emax-emin+1e-8f)*255.0f;
    float of=0.0f;
    if(m!=0.0f){
        const float* o=oriup+(size_t)b*CORI*NPIX+p;
        int ai=0; float bv=o[0];
        for(int ch=1;ch<CORI;ch++){ float v=o[(size_t)ch*NPIX]; if(v>bv){bv=v;ai=ch;} }
        of=((float)ai*2.0f-90.0f)*0.017453292519943295f*m;
    }
    out[ORI_OFF+i]=of;
}

extern "C" void kernel_launch(void* const* d_in, const int* in_sizes, int n_in,
                              void* d_out, int out_size){
    const float* seg    =(const float*)d_in[0];
    const float* segup  =(const float*)d_in[1];
    const float* oriup  =(const float*)d_in[2];
    const float* enh    =(const float*)d_in[3];
    const float* mscore =(const float*)d_in[4];
    const float* mori   =(const float*)d_in[5];
    const float* mxo    =(const float*)d_in[6];
    const float* myo    =(const float*)d_in[7];
    float* out=(float*)d_out;

    dim3 vg(WU/128, 13, BNUM);          // 13 segments of 40 rows
    dim3 hg(HU, BNUM);

    vpool<true ,true ,true ><<<vg,128>>>(segup, g_tA);            // vmin + rint + init
    hpool<true ,false><<<hg,256>>>(g_tA, g_tB, nullptr, nullptr); // hmin
    vpool<false,false,false><<<vg,128>>>(g_tB, g_tA);             // vmax
    hpool<false,true ><<<hg,256>>>(g_tA, g_maskup, enh, out);     // hmax + mask out + minmax

    detect_nms<<<BNUM,1024>>>(seg, mscore, mori, mxo, myo, out);

    int nBig=(BNUM*NPIX+255)/256;
    finalize<<<nBig,256>>>(enh, oriup, out);
}

// round 3
// speedup vs baseline: 1.1369x; 1.1369x over previous
#include <cuda_runtime.h>
#include <cstdint>

#define BNUM 4
#define HS 64
#define WS 64
#define HU 512
#define WU 512
#define CORI 90
#define CMNT 180
#define COFF 8
#define KCAND 1024
#define NCELL (HS*WS)       // 4096
#define NPIX (HU*WU)        // 262144

// output layout: minut [4,1024,4] | keep [4,1024] | enh_vis | mask_up*255 | ori_field
#define MINUT_OFF 0
#define KEEP_OFF  16384
#define ENH_OFF   20480
#define MASK_OFF  1069056
#define ORI_OFF   2117632

__device__ float g_mask[BNUM*NCELL];
__device__ float g_tA[BNUM*NPIX];
__device__ float g_tB[BNUM*NPIX];
__device__ float g_maskup[BNUM*NPIX];
__device__ unsigned g_emin[BNUM];
__device__ unsigned g_emax[BNUM];

__device__ __forceinline__ unsigned f2ord(float f){
    unsigned u=__float_as_uint(f);
    return (u & 0x80000000u) ? ~u : (u | 0x80000000u);
}
__device__ __forceinline__ float ord2f(unsigned u){
    u = (u & 0x80000000u) ? (u & 0x7fffffffu) : ~u;
    return __uint_as_float(u);
}

// ---------- fused 5x5 opening on [B,64,64]: one block per batch ----------
__global__ void __launch_bounds__(1024) opening_small(const float* __restrict__ seg){
    __shared__ float s0[NCELL];
    __shared__ float s1[NCELL];
    int b=blockIdx.x, tid=threadIdx.x;
    const float* sg=seg+(size_t)b*NCELL;
    for(int t=tid;t<NCELL;t+=1024) s0[t]=rintf(sg[t]);
    __syncthreads();
    for(int t=tid;t<NCELL;t+=1024){
        int r=t>>6, c=t&63;
        int y0=max(r-2,0), y1=min(r+2,HS-1), x0=max(c-2,0), x1=min(c+2,WS-1);
        float m=1e30f;
        for(int y=y0;y<=y1;y++)
            for(int x=x0;x<=x1;x++)
                m=fminf(m,s0[(y<<6)+x]);
        s1[t]=m;
    }
    __syncthreads();
    for(int t=tid;t<NCELL;t+=1024){
        int r=t>>6, c=t&63;
        int y0=max(r-2,0), y1=min(r+2,HS-1), x0=max(c-2,0), x1=min(c+2,WS-1);
        float m=-1e30f;
        for(int y=y0;y<=y1;y++)
            for(int x=x0;x<=x1;x++)
                m=fmaxf(m,s1[(y<<6)+x]);
        g_mask[(size_t)b*NCELL+t]=m;
    }
}

// ---------- vertical pool: van Herk with suffix in SHARED (spill-proof) ----------
// grid: (WU/128, 13 segments, BNUM), block 128. window [y-19, y+20].
template<bool MN, bool RND, bool INIT>
__global__ void __launch_bounds__(128) vpool(const float* __restrict__ in, float* __restrict__ outb){
    __shared__ float ssuf[40][128];
    if(INIT && blockIdx.x==0 && blockIdx.y==0 && blockIdx.z==0 && threadIdx.x<BNUM){
        g_emin[threadIdx.x]=0xFFFFFFFFu; g_emax[threadIdx.x]=0u;
    }
    int tid=threadIdx.x;
    int x = blockIdx.x*128 + tid;
    int y0 = blockIdx.y*40;
    int b = blockIdx.z;
    const float* s = in  + (size_t)b*NPIX;
    float*       o = outb+ (size_t)b*NPIX;
    const float NEU = MN?1e30f:-1e30f;
    float run = NEU;
    for(int d=39; d>=0; --d){
        int yy=y0-19+d;
        float v = (yy>=0 && yy<HU) ? s[yy*WU+x] : NEU;
        if(RND) v=rintf(v);
        run = MN?fminf(run,v):fmaxf(run,v);
        ssuf[d][tid]=run;   // each thread only reads its own column later
    }
    float pre = NEU;
    for(int j=0;j<40;j++){
        if(j>0){
            int yy=y0+20+j;
            float v = (yy<HU) ? s[yy*WU+x] : NEU;
            if(RND) v=rintf(v);
            pre = MN?fminf(pre,v):fmaxf(pre,v);
        }
        int y=y0+j;
        if(y<HU){
            float sv=ssuf[j][tid];
            o[y*WU+x] = MN?fminf(sv,pre):fmaxf(sv,pre);
        }
    }
}

// ---------- horizontal pool: log-doubling tree in shared ----------
template<bool MN, bool FUSED>
__global__ void __launch_bounds__(256) hpool(const float* __restrict__ in, float* __restrict__ outb,
                      const float* __restrict__ enh, float* __restrict__ outg){
    __shared__ float sA[552], sB[552], s8[552];
    __shared__ float rmn[8], rmx[8];
    int row = blockIdx.x, b = blockIdx.y, tid = threadIdx.x;
    const float* src = in + ((size_t)b*HU + row)*WU;
    const float NEU = MN?1e30f:-1e30f;
    #define OPX(a,c) (MN?fminf(a,c):fmaxf(a,c))
    for(int i=tid;i<551;i+=256) sA[i] = (i>=19 && i<19+WU) ? src[i-19] : NEU;
    __syncthreads();
    for(int i=tid;i<550;i+=256) sB[i]=OPX(sA[i],sA[i+1]);
    __syncthreads();
    for(int i=tid;i<548;i+=256) sA[i]=OPX(sB[i],sB[i+2]);
    __syncthreads();
    for(int i=tid;i<544;i+=256) s8[i]=OPX(sA[i],sA[i+4]);
    __syncthreads();
    for(int i=tid;i<536;i+=256) sB[i]=OPX(s8[i],s8[i+8]);
    __syncthreads();
    for(int i=tid;i<520;i+=256) sA[i]=OPX(sB[i],sB[i+16]);
    __syncthreads();
    float* dst = outb + ((size_t)b*HU+row)*WU;
    if(!FUSED){
        for(int x=tid;x<WU;x+=256) dst[x]=OPX(sA[x], s8[x+32]);
    } else {
        const float* erow = enh + ((size_t)b*HU+row)*WU;
        float mn=1e30f, mx=-1e30f;
        for(int x=tid;x<WU;x+=256){
            float m=OPX(sA[x], s8[x+32]);
            dst[x]=m;
            outg[MASK_OFF + ((size_t)b*HU+row)*WU + x] = m*255.0f;
            float ev = erow[x]*m;
            mn=fminf(mn,ev); mx=fmaxf(mx,ev);
        }
        #pragma unroll
        for(int o=16;o;o>>=1){
            mn=fminf(mn,__shfl_xor_sync(0xFFFFFFFFu,mn,o));
            mx=fmaxf(mx,__shfl_xor_sync(0xFFFFFFFFu,mx,o));
        }
        int lane=tid&31, w=tid>>5;
        if(lane==0){ rmn[w]=mn; rmx[w]=mx; }
        __syncthreads();
        if(tid==0){
            for(int i=1;i<8;i++){ mn=fminf(mn,rmn[i]); mx=fmaxf(mx,rmx[i]); }
            atomicMin(&g_emin[b], f2ord(mn));
            atomicMax(&g_emax[b], f2ord(mx));
        }
    }
    #undef OPX
}

// ---------- detect (R1-proven structure): top-k + NMS, one block per batch ----------
__global__ void __launch_bounds__(1024) detect_nms(
    const float* __restrict__ mscore, const float* __restrict__ mori,
    const float* __restrict__ mxo,    const float* __restrict__ myo,
    float* __restrict__ out)
{
    int b=blockIdx.x, tid=threadIdx.x;
    __shared__ unsigned long long keys[4096];   // 32KB
    __shared__ int s_nv;
    float* sx=(float*)(keys+1024);
    float* sy=(float*)(keys+1536);
    float* sa=(float*)(keys+2048);
    unsigned char* skeep=(unsigned char*)(keys+2560);

    const float* sc=mscore+(size_t)b*NCELL;
    const float* mk=g_mask +(size_t)b*NCELL;

    bool anyv=false;
    for(int t=tid;t<NCELL;t+=1024){
        float v=sc[t]*mk[t];
        bool val = v>0.5f;
        anyv |= val;
        float mv = val ? v : -1.0f;
        keys[t] = ((unsigned long long)(~f2ord(mv))<<32) | (unsigned)t;
    }
    if(__syncthreads_count(anyv)==0){
        float* om=out + MINUT_OFF + (size_t)b*KCAND*4 + (size_t)tid*4;
        om[0]=0.0f; om[1]=0.0f; om[2]=0.0f; om[3]=0.0f;
        out[KEEP_OFF + (size_t)b*KCAND + tid]=0.0f;
        return;
    }
    for(int k=2;k<=4096;k<<=1){
        for(int j=k>>1;j>0;j>>=1){
            for(int i=tid;i<4096;i+=1024){
                int ixj=i^j;
                if(ixj>i){
                    unsigned long long a=keys[i], c=keys[ixj];
                    bool up=((i&k)==0);
                    if((a>c)==up){ keys[i]=c; keys[ixj]=a; }
                }
            }
            __syncthreads();
        }
    }
    unsigned long long key=keys[tid];
    int idx=(int)(key & 0xFFFFFFFFull);
    float mv = ord2f(~(unsigned)(key>>32));
    bool valid = mv>0.5f;
    float score = valid ? mv : 0.0f;
    float xc=0.0f, yc=0.0f, ang=0.0f;
    if(valid){
        int r=idx>>6, c=idx&63;
        const float* o=mori+(size_t)b*CMNT*NCELL+idx;
        int ai=0; float bv=o[0];
        for(int ch=1;ch<CMNT;ch++){ float v=o[(size_t)ch*NCELL]; if(v>bv){bv=v;ai=ch;} }
        const float* xo=mxo+(size_t)b*COFF*NCELL+idx;
        int xi=0; float bx=xo[0];
        for(int ch=1;ch<COFF;ch++){ float v=xo[(size_t)ch*NCELL]; if(v>bx){bx=v;xi=ch;} }
        const float* yo=myo+(size_t)b*COFF*NCELL+idx;
        int yi=0; float by=yo[0];
        for(int ch=1;ch<COFF;ch++){ float v=yo[(size_t)ch*NCELL]; if(v>by){by=v;yi=ch;} }
        ang=((float)ai*2.0f-89.0f)*0.017453292519943295f;
        xc=(float)c*8.0f+(float)xi;
        yc=(float)r*8.0f+(float)yi;
    }
    if(tid==0) s_nv=0;
    __syncthreads();
    sx[tid]=xc; sy[tid]=yc; sa[tid]=ang; skeep[tid]=valid?1:0;
    atomicMax(&s_nv, valid?(tid+1):0);
    __syncthreads();
    int nv=s_nv;
    for(int i=0;i<nv;i++){
        if(skeep[i] && tid>i && skeep[tid]){
            float dx=sx[tid]-sx[i], dy=sy[tid]-sy[i];
            float d=sqrtf(dx*dx+dy*dy);
            float da=fabsf(sa[tid]-sa[i]);
            da=fminf(da, 6.2831853071795864f-da);
            if(d<16.0f && da<0.52359877559829887f) skeep[tid]=0;
        }
        __syncthreads();
    }
    float kf = skeep[tid]?1.0f:0.0f;
    float* om=out + MINUT_OFF + (size_t)b*KCAND*4 + (size_t)tid*4;
    om[0]=kf*xc; om[1]=kf*yc; om[2]=kf*ang; om[3]=kf*score;
    out[KEEP_OFF + (size_t)b*KCAND + tid]=kf;
}

// ---------- finalize: enh_vis + ori_field (mask-predicated) ----------
__global__ void __launch_bounds__(256) finalize(const float* __restrict__ enh,
                         const float* __restrict__ oriup, float* __restrict__ out){
    int i=blockIdx.x*blockDim.x+threadIdx.x;
    if(i>=BNUM*NPIX) return;
    int b=i/NPIX, p=i%NPIX;
    float m=g_maskup[i];
    float emin=ord2f(g_emin[b]);
    float emax=ord2f(g_emax[b]);
    float e=enh[i]*m;
    out[ENH_OFF+i]=(e-emin)/(emax-emin+1e-8f)*255.0f;
    float of=0.0f;
    if(m!=0.0f){
        const float* o=oriup+(size_t)b*CORI*NPIX+p;
        int ai=0; float bv=o[0];
        for(int ch=1;ch<CORI;ch++){ float v=o[(size_t)ch*NPIX]; if(v>bv){bv=v;ai=ch;} }
        of=((float)ai*2.0f-90.0f)*0.017453292519943295f*m;
    }
    out[ORI_OFF+i]=of;
}

extern "C" void kernel_launch(void* const* d_in, const int* in_sizes, int n_in,
                              void* d_out, int out_size){
    const float* seg    =(const float*)d_in[0];
    const float* segup  =(const float*)d_in[1];
    const float* oriup  =(const float*)d_in[2];
    const float* enh    =(const float*)d_in[3];
    const float* mscore =(const float*)d_in[4];
    const float* mori   =(const float*)d_in[5];
    const float* mxo    =(const float*)d_in[6];
    const float* myo    =(const float*)d_in[7];
    float* out=(float*)d_out;

    dim3 vg(WU/128, 13, BNUM);
    dim3 hg(HU, BNUM);

    opening_small<<<BNUM,1024>>>(seg);
    vpool<true ,true ,true ><<<vg,128>>>(segup, g_tA);            // vmin + rint + init
    hpool<true ,false><<<hg,256>>>(g_tA, g_tB, nullptr, nullptr); // hmin
    vpool<false,false,false><<<vg,128>>>(g_tB, g_tA);             // vmax
    hpool<false,true ><<<hg,256>>>(g_tA, g_maskup, enh, out);     // hmax + mask + minmax

    detect_nms<<<BNUM,1024>>>(mscore, mori, mxo, myo, out);

    int nBig=(BNUM*NPIX+255)/256;
    finalize<<<nBig,256>>>(enh, oriup, out);
}

// round 4
// speedup vs baseline: 1.1386x; 1.0015x over previous
#include <cuda_runtime.h>
#include <cstdint>

#define BNUM 4
#define HS 64
#define WS 64
#define HU 512
#define WU 512
#define CORI 90
#define CMNT 180
#define COFF 8
#define KCAND 1024
#define NCELL (HS*WS)       // 4096
#define NPIX (HU*WU)        // 262144

// output layout: minut [4,1024,4] | keep [4,1024] | enh_vis | mask_up*255 | ori_field
#define MINUT_OFF 0
#define KEEP_OFF  16384
#define ENH_OFF   20480
#define MASK_OFF  1069056
#define ORI_OFF   2117632

__device__ float g_mask[BNUM*NCELL];
__device__ float g_tA[BNUM*NPIX];
__device__ float g_tB[BNUM*NPIX];
__device__ float g_maskup[BNUM*NPIX];
__device__ unsigned g_emin[BNUM];
__device__ unsigned g_emax[BNUM];

__device__ __forceinline__ unsigned f2ord(float f){
    unsigned u=__float_as_uint(f);
    return (u & 0x80000000u) ? ~u : (u | 0x80000000u);
}
__device__ __forceinline__ float ord2f(unsigned u){
    u = (u & 0x80000000u) ? (u & 0x7fffffffu) : ~u;
    return __uint_as_float(u);
}

// ---------- fused 5x5 opening on [B,64,64]: one block per batch ----------
__global__ void __launch_bounds__(1024) opening_small(const float* __restrict__ seg){
    __shared__ float s0[NCELL];
    __shared__ float s1[NCELL];
    int b=blockIdx.x, tid=threadIdx.x;
    const float* sg=seg+(size_t)b*NCELL;
    for(int t=tid;t<NCELL;t+=1024) s0[t]=rintf(sg[t]);
    __syncthreads();
    for(int t=tid;t<NCELL;t+=1024){
        int r=t>>6, c=t&63;
        int y0=max(r-2,0), y1=min(r+2,HS-1), x0=max(c-2,0), x1=min(c+2,WS-1);
        float m=1e30f;
        for(int y=y0;y<=y1;y++)
            for(int x=x0;x<=x1;x++)
                m=fminf(m,s0[(y<<6)+x]);
        s1[t]=m;
    }
    __syncthreads();
    for(int t=tid;t<NCELL;t+=1024){
        int r=t>>6, c=t&63;
        int y0=max(r-2,0), y1=min(r+2,HS-1), x0=max(c-2,0), x1=min(c+2,WS-1);
        float m=-1e30f;
        for(int y=y0;y<=y1;y++)
            for(int x=x0;x<=x1;x++)
                m=fmaxf(m,s1[(y<<6)+x]);
        g_mask[(size_t)b*NCELL+t]=m;
    }
}

// ---------- vertical pool: van Herk with cooperative shared tile (high MLP) ----------
// grid: (WU/128, 13 segments, BNUM), block 128. window [y-19, y+20].
// tile rows 0..78 = global rows y0-19 .. y0+59. Each thread owns column tid;
// no cross-thread smem sharing -> zero __syncthreads in the hot path.
template<bool MN, bool RND, bool INIT>
__global__ void __launch_bounds__(128) vpool(const float* __restrict__ in, float* __restrict__ outb){
    __shared__ float tile[79][128];    // 40448 B
    if(INIT && blockIdx.x==0 && blockIdx.y==0 && blockIdx.z==0 && threadIdx.x<BNUM){
        g_emin[threadIdx.x]=0xFFFFFFFFu; g_emax[threadIdx.x]=0u;
    }
    int tid=threadIdx.x;
    int x  = blockIdx.x*128 + tid;
    int y0 = blockIdx.y*40;
    int b  = blockIdx.z;
    const float* s = in  + (size_t)b*NPIX + x;
    float*       o = outb+ (size_t)b*NPIX + x;
    const float NEU = MN?1e30f:-1e30f;

    // Phase 1: independent streaming loads -> shared (MLP-friendly)
    #pragma unroll 8
    for(int r=0;r<79;r++){
        int yy = y0-19+r;
        float v = (yy>=0 && yy<HU) ? __ldg(s + (size_t)yy*WU) : NEU;
        if(RND) v=rintf(v);
        tile[r][tid]=v;
    }
    // Phase 2: in-place suffix scan over tile rows 0..39 (own column only)
    {
        float run = tile[39][tid];
        #pragma unroll 8
        for(int d=38; d>=0; --d){
            float v = tile[d][tid];          // independent LDS
            run = MN?fminf(v,run):fmaxf(v,run);
            tile[d][tid] = run;
        }
    }
    // Phase 3: prefix + combine + store
    {
        float pre = NEU;
        #pragma unroll 8
        for(int j=0;j<40;j++){
            if(j>0){
                float v = tile[39+j][tid];   // global row y0+20+j
                pre = MN?fminf(pre,v):fmaxf(pre,v);
            }
            int y=y0+j;
            if(y<HU){
                float sv = tile[j][tid];
                o[(size_t)y*WU] = MN?fminf(sv,pre):fmaxf(sv,pre);
            }
        }
    }
}

// ---------- horizontal pool: log-doubling tree in shared ----------
template<bool MN, bool FUSED>
__global__ void __launch_bounds__(256) hpool(const float* __restrict__ in, float* __restrict__ outb,
                      const float* __restrict__ enh, float* __restrict__ outg){
    __shared__ float sA[552], sB[552], s8[552];
    __shared__ float rmn[8], rmx[8];
    int row = blockIdx.x, b = blockIdx.y, tid = threadIdx.x;
    const float* src = in + ((size_t)b*HU + row)*WU;
    const float NEU = MN?1e30f:-1e30f;
    #define OPX(a,c) (MN?fminf(a,c):fmaxf(a,c))
    for(int i=tid;i<551;i+=256) sA[i] = (i>=19 && i<19+WU) ? src[i-19] : NEU;
    __syncthreads();
    for(int i=tid;i<550;i+=256) sB[i]=OPX(sA[i],sA[i+1]);
    __syncthreads();
    for(int i=tid;i<548;i+=256) sA[i]=OPX(sB[i],sB[i+2]);
    __syncthreads();
    for(int i=tid;i<544;i+=256) s8[i]=OPX(sA[i],sA[i+4]);
    __syncthreads();
    for(int i=tid;i<536;i+=256) sB[i]=OPX(s8[i],s8[i+8]);
    __syncthreads();
    for(int i=tid;i<520;i+=256) sA[i]=OPX(sB[i],sB[i+16]);
    __syncthreads();
    float* dst = outb + ((size_t)b*HU+row)*WU;
    if(!FUSED){
        for(int x=tid;x<WU;x+=256) dst[x]=OPX(sA[x], s8[x+32]);
    } else {
        const float* erow = enh + ((size_t)b*HU+row)*WU;
        float mn=1e30f, mx=-1e30f;
        for(int x=tid;x<WU;x+=256){
            float m=OPX(sA[x], s8[x+32]);
            dst[x]=m;
            outg[MASK_OFF + ((size_t)b*HU+row)*WU + x] = m*255.0f;
            float ev = erow[x]*m;
            mn=fminf(mn,ev); mx=fmaxf(mx,ev);
        }
        #pragma unroll
        for(int o=16;o;o>>=1){
            mn=fminf(mn,__shfl_xor_sync(0xFFFFFFFFu,mn,o));
            mx=fmaxf(mx,__shfl_xor_sync(0xFFFFFFFFu,mx,o));
        }
        int lane=tid&31, w=tid>>5;
        if(lane==0){ rmn[w]=mn; rmx[w]=mx; }
        __syncthreads();
        if(tid==0){
            for(int i=1;i<8;i++){ mn=fminf(mn,rmn[i]); mx=fmaxf(mx,rmx[i]); }
            atomicMin(&g_emin[b], f2ord(mn));
            atomicMax(&g_emax[b], f2ord(mx));
        }
    }
    #undef OPX
}

// ---------- detect: top-k + NMS, one block per batch ----------
__global__ void __launch_bounds__(1024) detect_nms(
    const float* __restrict__ mscore, const float* __restrict__ mori,
    const float* __restrict__ mxo,    const float* __restrict__ myo,
    float* __restrict__ out)
{
    int b=blockIdx.x, tid=threadIdx.x;
    __shared__ unsigned long long keys[4096];   // 32KB
    __shared__ int s_nv;
    float* sx=(float*)(keys+1024);
    float* sy=(float*)(keys+1536);
    float* sa=(float*)(keys+2048);
    unsigned char* skeep=(unsigned char*)(keys+2560);

    const float* sc=mscore+(size_t)b*NCELL;
    const float* mk=g_mask +(size_t)b*NCELL;

    bool anyv=false;
    for(int t=tid;t<NCELL;t+=1024){
        float v=sc[t]*mk[t];
        bool val = v>0.5f;
        anyv |= val;
        float mv = val ? v : -1.0f;
        keys[t] = ((unsigned long long)(~f2ord(mv))<<32) | (unsigned)t;
    }
    if(__syncthreads_count(anyv)==0){
        float* om=out + MINUT_OFF + (size_t)b*KCAND*4 + (size_t)tid*4;
        om[0]=0.0f; om[1]=0.0f; om[2]=0.0f; om[3]=0.0f;
        out[KEEP_OFF + (size_t)b*KCAND + tid]=0.0f;
        return;
    }
    for(int k=2;k<=4096;k<<=1){
        for(int j=k>>1;j>0;j>>=1){
            for(int i=tid;i<4096;i+=1024){
                int ixj=i^j;
                if(ixj>i){
                    unsigned long long a=keys[i], c=keys[ixj];
                    bool up=((i&k)==0);
                    if((a>c)==up){ keys[i]=c; keys[ixj]=a; }
                }
            }
            __syncthreads();
        }
    }
    unsigned long long key=keys[tid];
    int idx=(int)(key & 0xFFFFFFFFull);
    float mv = ord2f(~(unsigned)(key>>32));
    bool valid = mv>0.5f;
    float score = valid ? mv : 0.0f;
    float xc=0.0f, yc=0.0f, ang=0.0f;
    if(valid){
        int r=idx>>6, c=idx&63;
        const float* o=mori+(size_t)b*CMNT*NCELL+idx;
        int ai=0; float bv=o[0];
        for(int ch=1;ch<CMNT;ch++){ float v=o[(size_t)ch*NCELL]; if(v>bv){bv=v;ai=ch;} }
        const float* xo=mxo+(size_t)b*COFF*NCELL+idx;
        int xi=0; float bx=xo[0];
        for(int ch=1;ch<COFF;ch++){ float v=xo[(size_t)ch*NCELL]; if(v>bx){bx=v;xi=ch;} }
        const float* yo=myo+(size_t)b*COFF*NCELL+idx;
        int yi=0; float by=yo[0];
        for(int ch=1;ch<COFF;ch++){ float v=yo[(size_t)ch*NCELL]; if(v>by){by=v;yi=ch;} }
        ang=((float)ai*2.0f-89.0f)*0.017453292519943295f;
        xc=(float)c*8.0f+(float)xi;
        yc=(float)r*8.0f+(float)yi;
    }
    if(tid==0) s_nv=0;
    __syncthreads();
    sx[tid]=xc; sy[tid]=yc; sa[tid]=ang; skeep[tid]=valid?1:0;
    atomicMax(&s_nv, valid?(tid+1):0);
    __syncthreads();
    int nv=s_nv;
    for(int i=0;i<nv;i++){
        if(skeep[i] && tid>i && skeep[tid]){
            float dx=sx[tid]-sx[i], dy=sy[tid]-sy[i];
            float d=sqrtf(dx*dx+dy*dy);
            float da=fabsf(sa[tid]-sa[i]);
            da=fminf(da, 6.2831853071795864f-da);
            if(d<16.0f && da<0.52359877559829887f) skeep[tid]=0;
        }
        __syncthreads();
    }
    float kf = skeep[tid]?1.0f:0.0f;
    float* om=out + MINUT_OFF + (size_t)b*KCAND*4 + (size_t)tid*4;
    om[0]=kf*xc; om[1]=kf*yc; om[2]=kf*ang; om[3]=kf*score;
    out[KEEP_OFF + (size_t)b*KCAND + tid]=kf;
}

// ---------- finalize: enh_vis + ori_field (mask-predicated) ----------
__global__ void __launch_bounds__(256) finalize(const float* __restrict__ enh,
                         const float* __restrict__ oriup, float* __restrict__ out){
    int i=blockIdx.x*blockDim.x+threadIdx.x;
    if(i>=BNUM*NPIX) return;
    int b=i/NPIX, p=i%NPIX;
    float m=g_maskup[i];
    float emin=ord2f(g_emin[b]);
    float emax=ord2f(g_emax[b]);
    float e=enh[i]*m;
    out[ENH_OFF+i]=(e-emin)/(emax-emin+1e-8f)*255.0f;
    float of=0.0f;
    if(m!=0.0f){
        const float* o=oriup+(size_t)b*CORI*NPIX+p;
        int ai=0; float bv=o[0];
        for(int ch=1;ch<CORI;ch++){ float v=o[(size_t)ch*NPIX]; if(v>bv){bv=v;ai=ch;} }
        of=((float)ai*2.0f-90.0f)*0.017453292519943295f*m;
    }
    out[ORI_OFF+i]=of;
}

extern "C" void kernel_launch(void* const* d_in, const int* in_sizes, int n_in,
                              void* d_out, int out_size){
    const float* seg    =(const float*)d_in[0];
    const float* segup  =(const float*)d_in[1];
    const float* oriup  =(const float*)d_in[2];
    const float* enh    =(const float*)d_in[3];
    const float* mscore =(const float*)d_in[4];
    const float* mori   =(const float*)d_in[5];
    const float* mxo    =(const float*)d_in[6];
    const float* myo    =(const float*)d_in[7];
    float* out=(float*)d_out;

    dim3 vg(WU/128, 13, BNUM);
    dim3 hg(HU, BNUM);

    opening_small<<<BNUM,1024>>>(seg);
    vpool<true ,true ,true ><<<vg,128>>>(segup, g_tA);            // vmin + rint + init
    hpool<true ,false><<<hg,256>>>(g_tA, g_tB, nullptr, nullptr); // hmin
    vpool<false,false,false><<<vg,128>>>(g_tB, g_tA);             // vmax
    hpool<false,true ><<<hg,256>>>(g_tA, g_maskup, enh, out);     // hmax + mask + minmax

    detect_nms<<<BNUM,1024>>>(mscore, mori, mxo, myo, out);

    int nBig=(BNUM*NPIX+255)/256;
    finalize<<<nBig,256>>>(enh, oriup, out);
}

// round 5
// speedup vs baseline: 1.1574x; 1.0164x over previous
#include <cuda_runtime.h>
#include <cstdint>

#define BNUM 4
#define HS 64
#define WS 64
#define HU 512
#define WU 512
#define CORI 90
#define CMNT 180
#define COFF 8
#define KCAND 1024
#define NCELL (HS*WS)       // 4096
#define NPIX (HU*WU)        // 262144

// output layout: minut [4,1024,4] | keep [4,1024] | enh_vis | mask_up*255 | ori_field
#define MINUT_OFF 0
#define KEEP_OFF  16384
#define ENH_OFF   20480
#define MASK_OFF  1069056
#define ORI_OFF   2117632

__device__ float g_mask[BNUM*NCELL];
__device__ float g_tA[BNUM*NPIX];
__device__ float g_tB[BNUM*NPIX];
__device__ float g_maskup[BNUM*NPIX];
__device__ unsigned g_emin[BNUM];
__device__ unsigned g_emax[BNUM];

__device__ __forceinline__ unsigned f2ord(float f){
    unsigned u=__float_as_uint(f);
    return (u & 0x80000000u) ? ~u : (u | 0x80000000u);
}
__device__ __forceinline__ float ord2f(unsigned u){
    u = (u & 0x80000000u) ? (u & 0x7fffffffu) : ~u;
    return __uint_as_float(u);
}

// ---------- fused 5x5 opening on [B,64,64]: one block per batch ----------
__global__ void __launch_bounds__(1024) opening_small(const float* __restrict__ seg){
    __shared__ float s0[NCELL];
    __shared__ float s1[NCELL];
    int b=blockIdx.x, tid=threadIdx.x;
    const float* sg=seg+(size_t)b*NCELL;
    for(int t=tid;t<NCELL;t+=1024) s0[t]=rintf(sg[t]);
    __syncthreads();
    for(int t=tid;t<NCELL;t+=1024){
        int r=t>>6, c=t&63;
        int y0=max(r-2,0), y1=min(r+2,HS-1), x0=max(c-2,0), x1=min(c+2,WS-1);
        float m=1e30f;
        for(int y=y0;y<=y1;y++)
            for(int x=x0;x<=x1;x++)
                m=fminf(m,s0[(y<<6)+x]);
        s1[t]=m;
    }
    __syncthreads();
    for(int t=tid;t<NCELL;t+=1024){
        int r=t>>6, c=t&63;
        int y0=max(r-2,0), y1=min(r+2,HS-1), x0=max(c-2,0), x1=min(c+2,WS-1);
        float m=-1e30f;
        for(int y=y0;y<=y1;y++)
            for(int x=x0;x<=x1;x++)
                m=fmaxf(m,s1[(y<<6)+x]);
        g_mask[(size_t)b*NCELL+t]=m;
    }
}

// ---------- vertical pool: cooperative doubling tree, 1024 threads/block ----------
// grid (4 xtiles, 13 ysegs, BNUM). tile = 79 rows x 128 cols (rows y0-19..y0+59).
// win40 over rows [r, r+39]  ==  op(r32[r], r8[r+32]).
// dynamic smem: sA 79 rows | sB 78 rows | sC 48 rows  (flat row*128+col)
#define VROWS 79
#define VA 0
#define VB (79*128)
#define VC (VB+78*128)
#define VSMEM ((79+78+48)*128*4)
template<bool MN, bool RND, bool INIT>
__global__ void __launch_bounds__(1024) vpool(const float* __restrict__ in, float* __restrict__ outb){
    extern __shared__ float sm[];
    float* sA=sm+VA; float* sB=sm+VB; float* sC=sm+VC;
    if(INIT && blockIdx.x==0 && blockIdx.y==0 && blockIdx.z==0 && threadIdx.x<BNUM){
        g_emin[threadIdx.x]=0xFFFFFFFFu; g_emax[threadIdx.x]=0u;
    }
    int tid=threadIdx.x;
    int xt = blockIdx.x*128;
    int y0 = blockIdx.y*40;
    int b  = blockIdx.z;
    const float* src = in + (size_t)b*NPIX + xt;
    const float NEU = MN?1e30f:-1e30f;
    #define OPX(a,c) (MN?fminf(a,c):fmaxf(a,c))
    // load 79 rows (coalesced, independent)
    #pragma unroll
    for(int i=tid;i<79*128;i+=1024){
        int r=i>>7, c=i&127;
        int yy=y0-19+r;
        float v=(yy>=0 && yy<HU)? src[(size_t)yy*WU+c] : NEU;
        if(RND) v=rintf(v);
        sA[i]=v;
    }
    __syncthreads();
    #pragma unroll
    for(int i=tid;i<78*128;i+=1024) sB[i]=OPX(sA[i],sA[i+128]);    // r2
    __syncthreads();
    #pragma unroll
    for(int i=tid;i<76*128;i+=1024) sA[i]=OPX(sB[i],sB[i+256]);    // r4
    __syncthreads();
    #pragma unroll
    for(int i=tid;i<72*128;i+=1024) sB[i]=OPX(sA[i],sA[i+512]);    // r8 (kept)
    __syncthreads();
    #pragma unroll
    for(int i=tid;i<64*128;i+=1024) sA[i]=OPX(sB[i],sB[i+1024]);   // r16
    __syncthreads();
    #pragma unroll
    for(int i=tid;i<48*128;i+=1024) sC[i]=OPX(sA[i],sA[i+2048]);   // r32
    __syncthreads();
    float* dst = outb + (size_t)b*NPIX + xt;
    #pragma unroll
    for(int i=tid;i<40*128;i+=1024){
        int r=i>>7, c=i&127;
        int y=y0+r;
        if(y<HU) dst[(size_t)y*WU+c]=OPX(sC[i], sB[i+32*128]);
    }
    #undef OPX
}

// ---------- horizontal pool: log-doubling tree in shared ----------
template<bool MN, bool FUSED>
__global__ void __launch_bounds__(256) hpool(const float* __restrict__ in, float* __restrict__ outb,
                      const float* __restrict__ enh, float* __restrict__ outg){
    __shared__ float sA[552], sB[552], s8[552];
    __shared__ float rmn[8], rmx[8];
    int row = blockIdx.x, b = blockIdx.y, tid = threadIdx.x;
    const float* src = in + ((size_t)b*HU + row)*WU;
    const float NEU = MN?1e30f:-1e30f;
    #define OPX(a,c) (MN?fminf(a,c):fmaxf(a,c))
    for(int i=tid;i<551;i+=256) sA[i] = (i>=19 && i<19+WU) ? src[i-19] : NEU;
    __syncthreads();
    for(int i=tid;i<550;i+=256) sB[i]=OPX(sA[i],sA[i+1]);
    __syncthreads();
    for(int i=tid;i<548;i+=256) sA[i]=OPX(sB[i],sB[i+2]);
    __syncthreads();
    for(int i=tid;i<544;i+=256) s8[i]=OPX(sA[i],sA[i+4]);
    __syncthreads();
    for(int i=tid;i<536;i+=256) sB[i]=OPX(s8[i],s8[i+8]);
    __syncthreads();
    for(int i=tid;i<520;i+=256) sA[i]=OPX(sB[i],sB[i+16]);
    __syncthreads();
    float* dst = outb + ((size_t)b*HU+row)*WU;
    if(!FUSED){
        for(int x=tid;x<WU;x+=256) dst[x]=OPX(sA[x], s8[x+32]);
    } else {
        const float* erow = enh + ((size_t)b*HU+row)*WU;
        float mn=1e30f, mx=-1e30f;
        for(int x=tid;x<WU;x+=256){
            float m=OPX(sA[x], s8[x+32]);
            dst[x]=m;
            outg[MASK_OFF + ((size_t)b*HU+row)*WU + x] = m*255.0f;
            float ev = erow[x]*m;
            mn=fminf(mn,ev); mx=fmaxf(mx,ev);
        }
        #pragma unroll
        for(int o=16;o;o>>=1){
            mn=fminf(mn,__shfl_xor_sync(0xFFFFFFFFu,mn,o));
            mx=fmaxf(mx,__shfl_xor_sync(0xFFFFFFFFu,mx,o));
        }
        int lane=tid&31, w=tid>>5;
        if(lane==0){ rmn[w]=mn; rmx[w]=mx; }
        __syncthreads();
        if(tid==0){
            for(int i=1;i<8;i++){ mn=fminf(mn,rmn[i]); mx=fmaxf(mx,rmx[i]); }
            atomicMin(&g_emin[b], f2ord(mn));
            atomicMax(&g_emax[b], f2ord(mx));
        }
    }
    #undef OPX
}

// ---------- detect: top-k + NMS, one block per batch ----------
__global__ void __launch_bounds__(1024) detect_nms(
    const float* __restrict__ mscore, const float* __restrict__ mori,
    const float* __restrict__ mxo,    const float* __restrict__ myo,
    float* __restrict__ out)
{
    int b=blockIdx.x, tid=threadIdx.x;
    __shared__ unsigned long long keys[4096];   // 32KB
    __shared__ int s_nv;
    float* sx=(float*)(keys+1024);
    float* sy=(float*)(keys+1536);
    float* sa=(float*)(keys+2048);
    unsigned char* skeep=(unsigned char*)(keys+2560);

    const float* sc=mscore+(size_t)b*NCELL;
    const float* mk=g_mask +(size_t)b*NCELL;

    bool anyv=false;
    for(int t=tid;t<NCELL;t+=1024){
        float v=sc[t]*mk[t];
        bool val = v>0.5f;
        anyv |= val;
        float mv = val ? v : -1.0f;
        keys[t] = ((unsigned long long)(~f2ord(mv))<<32) | (unsigned)t;
    }
    if(__syncthreads_count(anyv)==0){
        float* om=out + MINUT_OFF + (size_t)b*KCAND*4 + (size_t)tid*4;
        om[0]=0.0f; om[1]=0.0f; om[2]=0.0f; om[3]=0.0f;
        out[KEEP_OFF + (size_t)b*KCAND + tid]=0.0f;
        return;
    }
    for(int k=2;k<=4096;k<<=1){
        for(int j=k>>1;j>0;j>>=1){
            for(int i=tid;i<4096;i+=1024){
                int ixj=i^j;
                if(ixj>i){
                    unsigned long long a=keys[i], c=keys[ixj];
                    bool up=((i&k)==0);
                    if((a>c)==up){ keys[i]=c; keys[ixj]=a; }
                }
            }
            __syncthreads();
        }
    }
    unsigned long long key=keys[tid];
    int idx=(int)(key & 0xFFFFFFFFull);
    float mv = ord2f(~(unsigned)(key>>32));
    bool valid = mv>0.5f;
    float score = valid ? mv : 0.0f;
    float xc=0.0f, yc=0.0f, ang=0.0f;
    if(valid){
        int r=idx>>6, c=idx&63;
        const float* o=mori+(size_t)b*CMNT*NCELL+idx;
        int ai=0; float bv=o[0];
        for(int ch=1;ch<CMNT;ch++){ float v=o[(size_t)ch*NCELL]; if(v>bv){bv=v;ai=ch;} }
        const float* xo=mxo+(size_t)b*COFF*NCELL+idx;
        int xi=0; float bx=xo[0];
        for(int ch=1;ch<COFF;ch++){ float v=xo[(size_t)ch*NCELL]; if(v>bx){bx=v;xi=ch;} }
        const float* yo=myo+(size_t)b*COFF*NCELL+idx;
        int yi=0; float by=yo[0];
        for(int ch=1;ch<COFF;ch++){ float v=yo[(size_t)ch*NCELL]; if(v>by){by=v;yi=ch;} }
        ang=((float)ai*2.0f-89.0f)*0.017453292519943295f;
        xc=(float)c*8.0f+(float)xi;
        yc=(float)r*8.0f+(float)yi;
    }
    if(tid==0) s_nv=0;
    __syncthreads();
    sx[tid]=xc; sy[tid]=yc; sa[tid]=ang; skeep[tid]=valid?1:0;
    atomicMax(&s_nv, valid?(tid+1):0);
    __syncthreads();
    int nv=s_nv;
    for(int i=0;i<nv;i++){
        if(skeep[i] && tid>i && skeep[tid]){
            float dx=sx[tid]-sx[i], dy=sy[tid]-sy[i];
            float d=sqrtf(dx*dx+dy*dy);
            float da=fabsf(sa[tid]-sa[i]);
            da=fminf(da, 6.2831853071795864f-da);
            if(d<16.0f && da<0.52359877559829887f) skeep[tid]=0;
        }
        __syncthreads();
    }
    float kf = skeep[tid]?1.0f:0.0f;
    float* om=out + MINUT_OFF + (size_t)b*KCAND*4 + (size_t)tid*4;
    om[0]=kf*xc; om[1]=kf*yc; om[2]=kf*ang; om[3]=kf*score;
    out[KEEP_OFF + (size_t)b*KCAND + tid]=kf;
}

// ---------- finalize: enh_vis + ori_field (mask-predicated) ----------
__global__ void __launch_bounds__(256) finalize(const float* __restrict__ enh,
                         const float* __restrict__ oriup, float* __restrict__ out){
    int i=blockIdx.x*blockDim.x+threadIdx.x;
    if(i>=BNUM*NPIX) return;
    int b=i/NPIX, p=i%NPIX;
    float m=g_maskup[i];
    float emin=ord2f(g_emin[b]);
    float emax=ord2f(g_emax[b]);
    float e=enh[i]*m;
    out[ENH_OFF+i]=(e-emin)/(emax-emin+1e-8f)*255.0f;
    float of=0.0f;
    if(m!=0.0f){
        const float* o=oriup+(size_t)b*CORI*NPIX+p;
        int ai=0; float bv=o[0];
        for(int ch=1;ch<CORI;ch++){ float v=o[(size_t)ch*NPIX]; if(v>bv){bv=v;ai=ch;} }
        of=((float)ai*2.0f-90.0f)*0.017453292519943295f*m;
    }
    out[ORI_OFF+i]=of;
}

extern "C" void kernel_launch(void* const* d_in, const int* in_sizes, int n_in,
                              void* d_out, int out_size){
    const float* seg    =(const float*)d_in[0];
    const float* segup  =(const float*)d_in[1];
    const float* oriup  =(const float*)d_in[2];
    const float* enh    =(const float*)d_in[3];
    const float* mscore =(const float*)d_in[4];
    const float* mori   =(const float*)d_in[5];
    const float* mxo    =(const float*)d_in[6];
    const float* myo    =(const float*)d_in[7];
    float* out=(float*)d_out;

    // allow >48KB dynamic smem (host attribute set; no allocation, capture-safe)
    static int attr_done=0;
    if(!attr_done){
        cudaFuncSetAttribute(vpool<true ,true ,true >, cudaFuncAttributeMaxDynamicSharedMemorySize, VSMEM);
        cudaFuncSetAttribute(vpool<false,false,false>, cudaFuncAttributeMaxDynamicSharedMemorySize, VSMEM);
        attr_done=1;
    }

    dim3 vg(WU/128, 13, BNUM);
    dim3 hg(HU, BNUM);

    opening_small<<<BNUM,1024>>>(seg);
    vpool<true ,true ,true ><<<vg,1024,VSMEM>>>(segup, g_tA);      // vmin + rint + init
    hpool<true ,false><<<hg,256>>>(g_tA, g_tB, nullptr, nullptr);  // hmin
    vpool<false,false,false><<<vg,1024,VSMEM>>>(g_tB, g_tA);       // vmax
    hpool<false,true ><<<hg,256>>>(g_tA, g_maskup, enh, out);      // hmax + mask + minmax

    detect_nms<<<BNUM,1024>>>(mscore, mori, mxo, myo, out);

    int nBig=(BNUM*NPIX+255)/256;
    finalize<<<nBig,256>>>(enh, oriup, out);
}